// round 10
// baseline (speedup 1.0000x reference)
#include <cuda_runtime.h>
#include <cstdint>
#include <math.h>

// Shapes
#define BATCH 64
#define FEAT  2048
#define EDIM  64

// 16 batch groups x 8 feature chunks = 128 CTAs; each 8-CTA cluster covers one
// batch group (4 rows) and combines partials in the leader's SMEM via DSMEM.
#define NB_ROWS 4
#define CLUSTER 8
#define FCHUNK  (FEAT / CLUSTER)                 // 256
#define GRID    ((BATCH / NB_ROWS) * CLUSTER)    // 128
#define NTHREADS 512

__device__ __forceinline__ uint32_t smem_u32(const void* p) {
    uint32_t a;
    asm("{ .reg .u64 t; cvta.to.shared.u64 t, %1; cvt.u32.u64 %0, t; }"
        : "=r"(a) : "l"(p));
    return a;
}

// Store one f32 into cluster-rank-0's SMEM at the same offset as `local_addr`.
__device__ __forceinline__ void dsmem_st_leader_f32(uint32_t local_addr, float v) {
    uint32_t remote;
    asm volatile("mapa.shared::cluster.u32 %0, %1, 0;" : "=r"(remote) : "r"(local_addr));
    asm volatile("st.shared::cluster.f32 [%0], %1;" :: "r"(remote), "f"(v) : "memory");
}

__global__ void __cluster_dims__(CLUSTER, 1, 1) __launch_bounds__(NTHREADS, 1)
fm_cluster(const float* __restrict__ data,    // (BATCH, FEAT)
           const float* __restrict__ embed,   // (FEAT, EDIM)
           const float* __restrict__ bias,    // (FEAT,)
           const float* __restrict__ gbias,   // (1,)
           float* __restrict__ out)           // (BATCH,)
{
    __shared__ float sh_x[NB_ROWS][FCHUNK];          //  4 KB
    __shared__ float shp[32][NB_ROWS][EDIM + 4];     // ~34 KB (pad kills conflicts)
    __shared__ float red_S[CLUSTER][NB_ROWS][EDIM];  //  8 KB  (leader receives)
    __shared__ float red_L[CLUSTER][NB_ROWS];        //  128 B (leader receives)
    __shared__ float linT[NB_ROWS][2];
    __shared__ float fin[NB_ROWS][2];

    const int tid = threadIdx.x;
    uint32_t rank;
    asm("mov.u32 %0, %%cluster_ctarank;" : "=r"(rank));
    const int bg = blockIdx.x / CLUSTER;   // batch group 0..15
    const int fc = (int)rank;              // feature chunk 0..7
    const int b0 = bg * NB_ROWS;
    const int f0 = fc * FCHUNK;

    // --- Prefetch embed into registers FIRST: these LDGs have no dependence
    // on sh_x, and a barrier would otherwise serialize them behind the x-load.
    const int fg = tid >> 4;
    const int dq = tid & 15;
    const int d0 = dq * 4;

    float4 v[8];
#pragma unroll
    for (int j = 0; j < 8; j++) {
        const int fl = fg * 8 + j;
        v[j] = *reinterpret_cast<const float4*>(&embed[(f0 + fl) * EDIM + d0]);
    }

    // --- Concurrently: tid<256 stage x into shared; tid>=256 compute the
    // linear-term partial straight from global (no sh_x dependency). ---
    if (tid < 256) {
        const int r = tid >> 6, c = tid & 63;
        float4 x4 = *reinterpret_cast<const float4*>(&data[(b0 + r) * FEAT + f0 + c * 4]);
        *reinterpret_cast<float4*>(&sh_x[r][c * 4]) = x4;
    } else {
        const int t2 = tid - 256;
        const int r = t2 >> 6, c = t2 & 63;
        const float4 xx = *reinterpret_cast<const float4*>(&data[(b0 + r) * FEAT + f0 + c * 4]);
        const float4 bb = *reinterpret_cast<const float4*>(&bias[f0 + c * 4]);
        float p = xx.x * bb.x + xx.y * bb.y + xx.z * bb.z + xx.w * bb.w;
#pragma unroll
        for (int o = 16; o; o >>= 1) p += __shfl_xor_sync(0xffffffffu, p, o);
        if ((t2 & 31) == 0) linT[r][(t2 >> 5) & 1] = p;
    }
    __syncthreads();

    // --- Stage B: partial GEMM from registers. 1 prefetched float4 of V feeds
    // 16 FFMA (4 rows x 4 d). All 512 threads (fg 0..31). ---
    float acc[NB_ROWS][4];
#pragma unroll
    for (int r = 0; r < NB_ROWS; r++)
#pragma unroll
        for (int i = 0; i < 4; i++) acc[r][i] = 0.0f;

#pragma unroll
    for (int j = 0; j < 8; j++) {
        const int fl = fg * 8 + j;
#pragma unroll
        for (int r = 0; r < NB_ROWS; r++) {
            const float xf = sh_x[r][fl];
            acc[r][0] = fmaf(xf, v[j].x, acc[r][0]);
            acc[r][1] = fmaf(xf, v[j].y, acc[r][1]);
            acc[r][2] = fmaf(xf, v[j].z, acc[r][2]);
            acc[r][3] = fmaf(xf, v[j].w, acc[r][3]);
        }
    }

#pragma unroll
    for (int r = 0; r < NB_ROWS; r++) {
        float4 w;
        w.x = acc[r][0]; w.y = acc[r][1]; w.z = acc[r][2]; w.w = acc[r][3];
        *reinterpret_cast<float4*>(&shp[fg][r][d0]) = w;
    }
    __syncthreads();

    // --- Stage C: tid<256 reduce the 32 fg-partials -> partial S; ship to the
    // leader (plain STS if we ARE the leader, DSMEM otherwise).
    // tid 256..259 combine linT halves -> partial lin; ship likewise. ---
    if (tid < 256) {
        const int r = tid >> 6, d = tid & 63;
        float s = 0.0f;
#pragma unroll
        for (int g = 0; g < 32; g++) s += shp[g][r][d];
        if (rank == 0) red_S[fc][r][d] = s;
        else           dsmem_st_leader_f32(smem_u32(&red_S[fc][r][d]), s);
    } else if (tid < 256 + NB_ROWS) {
        const int r = tid - 256;
        const float l = linT[r][0] + linT[r][1];
        if (rank == 0) red_L[fc][r] = l;
        else           dsmem_st_leader_f32(smem_u32(&red_L[fc][r]), l);
    }

    // --- Cluster barrier: arrive releases our DSMEM stores; wait acquires
    // everyone's. (Leader's plain STS are ordered by its own arrive too.) ---
    asm volatile("barrier.cluster.arrive.aligned;" ::: "memory");
    asm volatile("barrier.cluster.wait.aligned;"   ::: "memory");

    if (rank != 0) return;

    // --- Leader epilogue: combine 8 chunk-partials, square-sum over d,
    // add linear + global bias, sigmoid. ---
    if (tid < 256) {
        const int r = tid >> 6, d = tid & 63;
        float s = 0.0f;
#pragma unroll
        for (int k = 0; k < CLUSTER; k++) s += red_S[k][r][d];
        float sq = s * s;
#pragma unroll
        for (int o = 16; o; o >>= 1) sq += __shfl_xor_sync(0xffffffffu, sq, o);
        if ((tid & 31) == 0) fin[r][(tid >> 5) & 1] = sq;
    }
    __syncthreads();

    if (tid < NB_ROWS) {
        float lin = 0.0f;
#pragma unroll
        for (int k = 0; k < CLUSTER; k++) lin += red_L[k][tid];
        const float z = gbias[0] + lin + fin[tid][0] + fin[tid][1];
        out[b0 + tid] = 1.0f / (1.0f + __expf(-z));
    }
}

extern "C" void kernel_launch(void* const* d_in, const int* in_sizes, int n_in,
                              void* d_out, int out_size) {
    const float* data  = (const float*)d_in[0];
    const float* embed = (const float*)d_in[1];
    const float* bias  = (const float*)d_in[2];
    const float* gbias = (const float*)d_in[3];
    float* out = (float*)d_out;

    fm_cluster<<<GRID, NTHREADS>>>(data, embed, bias, gbias, out);
}

// round 12
// speedup vs baseline: 1.1776x; 1.1776x over previous
#include <cuda_runtime.h>
#include <cstdint>
#include <math.h>

// Shapes
#define BATCH 64
#define FEAT  2048
#define EDIM  64

// 16 batch groups x 8 feature chunks = 128 CTAs; each 8-CTA cluster covers one
// batch group (4 rows), combines partials in the leader's SMEM via DSMEM.
#define NB_ROWS 4
#define CLUSTER 8
#define FCHUNK  (FEAT / CLUSTER)                 // 256
#define GRID    ((BATCH / NB_ROWS) * CLUSTER)    // 128
#define NTHREADS 256                             // 16 fg x 16 dq

__device__ __forceinline__ uint32_t smem_u32(const void* p) {
    uint32_t a;
    asm("{ .reg .u64 t; cvta.to.shared.u64 t, %1; cvt.u32.u64 %0, t; }"
        : "=r"(a) : "l"(p));
    return a;
}

// Store one f32 into cluster-rank-0's SMEM at the same offset as `local_addr`.
__device__ __forceinline__ void dsmem_st_leader_f32(uint32_t local_addr, float v) {
    uint32_t remote;
    asm volatile("mapa.shared::cluster.u32 %0, %1, 0;" : "=r"(remote) : "r"(local_addr));
    asm volatile("st.shared::cluster.f32 [%0], %1;" :: "r"(remote), "f"(v) : "memory");
}

__global__ void __cluster_dims__(CLUSTER, 1, 1) __launch_bounds__(NTHREADS, 1)
fm_cluster(const float* __restrict__ data,    // (BATCH, FEAT)
           const float* __restrict__ embed,   // (FEAT, EDIM)
           const float* __restrict__ bias,    // (FEAT,)
           const float* __restrict__ gbias,   // (1,)
           float* __restrict__ out)           // (BATCH,)
{
    __shared__ float sh_x[NB_ROWS][FCHUNK];          //  4 KB
    __shared__ float shp[16][NB_ROWS][EDIM + 4];     // ~17 KB (pad: float4 align + banks)
    __shared__ float red_S[CLUSTER][NB_ROWS][EDIM];  //  8 KB  (leader receives)
    __shared__ float red_L[CLUSTER][NB_ROWS];        //  128 B (leader receives)
    __shared__ float linT[NB_ROWS][2];
    __shared__ float fin[NB_ROWS][2];

    const int tid = threadIdx.x;
    uint32_t rank;
    asm("mov.u32 %0, %%cluster_ctarank;" : "=r"(rank));
    const int bg = blockIdx.x / CLUSTER;   // batch group 0..15
    const int fc = (int)rank;              // feature chunk 0..7
    const int b0 = bg * NB_ROWS;
    const int f0 = fc * FCHUNK;

    // --- Prefetch embed into registers FIRST (no dependence on sh_x; issuing
    // these LDGs before anything else overlaps both memory rounds). ---
    const int fg = tid >> 4;       // 0..15, 16 features each
    const int dq = tid & 15;       // 0..15
    const int d0 = dq * 4;

    float4 v[16];
#pragma unroll
    for (int j = 0; j < 16; j++) {
        const int fl = fg * 16 + j;
        v[j] = *reinterpret_cast<const float4*>(&embed[(f0 + fl) * EDIM + d0]);
    }

    // --- Concurrently: every thread loads one x float4 (stages it in shared)
    // AND folds its bias dot-product for the linear term. ---
    {
        const int r = tid >> 6, c = tid & 63;
        const float4 x4 = *reinterpret_cast<const float4*>(&data[(b0 + r) * FEAT + f0 + c * 4]);
        *reinterpret_cast<float4*>(&sh_x[r][c * 4]) = x4;
        const float4 bb = *reinterpret_cast<const float4*>(&bias[f0 + c * 4]);
        float p = x4.x * bb.x + x4.y * bb.y + x4.z * bb.z + x4.w * bb.w;
#pragma unroll
        for (int o = 16; o; o >>= 1) p += __shfl_xor_sync(0xffffffffu, p, o);
        if ((tid & 31) == 0) linT[r][(tid >> 5) & 1] = p;   // warp w -> r = w>>1
    }
    __syncthreads();

    // --- Partial GEMM from registers: each prefetched float4 feeds 16 FFMA. ---
    float acc[NB_ROWS][4];
#pragma unroll
    for (int r = 0; r < NB_ROWS; r++)
#pragma unroll
        for (int i = 0; i < 4; i++) acc[r][i] = 0.0f;

#pragma unroll
    for (int j = 0; j < 16; j++) {
        const int fl = fg * 16 + j;
#pragma unroll
        for (int r = 0; r < NB_ROWS; r++) {
            const float xf = sh_x[r][fl];
            acc[r][0] = fmaf(xf, v[j].x, acc[r][0]);
            acc[r][1] = fmaf(xf, v[j].y, acc[r][1]);
            acc[r][2] = fmaf(xf, v[j].z, acc[r][2]);
            acc[r][3] = fmaf(xf, v[j].w, acc[r][3]);
        }
    }

#pragma unroll
    for (int r = 0; r < NB_ROWS; r++) {
        float4 w;
        w.x = acc[r][0]; w.y = acc[r][1]; w.z = acc[r][2]; w.w = acc[r][3];
        *reinterpret_cast<float4*>(&shp[fg][r][d0]) = w;
    }
    __syncthreads();

    // --- Cross-fg reduce -> partial S; ship to leader (plain STS if leader). ---
    {
        const int r = tid >> 6, d = tid & 63;
        float s = 0.0f;
#pragma unroll
        for (int g = 0; g < 16; g++) s += shp[g][r][d];
        if (rank == 0) red_S[fc][r][d] = s;
        else           dsmem_st_leader_f32(smem_u32(&red_S[fc][r][d]), s);
    }
    if (tid < NB_ROWS) {
        const float l = linT[tid][0] + linT[tid][1];
        if (rank == 0) red_L[fc][tid] = l;
        else           dsmem_st_leader_f32(smem_u32(&red_L[fc][tid]), l);
    }

    // --- Combine sync: every thread's arrive releases its own DSMEM stores.
    // Non-leaders arrive and EXIT (no wait); only the leader waits, which also
    // serves as the leader's CTA-wide barrier before reading red_S/red_L. ---
    asm volatile("barrier.cluster.arrive.aligned;" ::: "memory");
    if (rank != 0) return;
    asm volatile("barrier.cluster.wait.aligned;"   ::: "memory");

    // --- Leader epilogue: combine 8 chunk-partials, square-sum over d,
    // add linear + global bias, sigmoid. ---
    {
        const int r = tid >> 6, d = tid & 63;
        float s = 0.0f;
#pragma unroll
        for (int k = 0; k < CLUSTER; k++) s += red_S[k][r][d];
        float sq = s * s;
#pragma unroll
        for (int o = 16; o; o >>= 1) sq += __shfl_xor_sync(0xffffffffu, sq, o);
        if ((tid & 31) == 0) fin[r][(tid >> 5) & 1] = sq;
    }
    __syncthreads();

    if (tid < NB_ROWS) {
        float lin = 0.0f;
#pragma unroll
        for (int k = 0; k < CLUSTER; k++) lin += red_L[k][tid];
        const float z = gbias[0] + lin + fin[tid][0] + fin[tid][1];
        out[b0 + tid] = 1.0f / (1.0f + __expf(-z));
    }
}

extern "C" void kernel_launch(void* const* d_in, const int* in_sizes, int n_in,
                              void* d_out, int out_size) {
    const float* data  = (const float*)d_in[0];
    const float* embed = (const float*)d_in[1];
    const float* bias  = (const float*)d_in[2];
    const float* gbias = (const float*)d_in[3];
    float* out = (float*)d_out;

    fm_cluster<<<GRID, NTHREADS>>>(data, embed, bias, gbias, out);
}